// round 7
// baseline (speedup 1.0000x reference)
#include <cuda_runtime.h>

// RNN_13855564496941: Euler RNN, T=1024, B=4096, H=50.
// R7 (= R6 resubmit; prior round was an infra failure, kernel never ran):
//   j-split across 2 warps -> 25 f32x2 weight regs/lane -> ~12 CTAs/SM,
//   24 warps/SM (6/SMSP) for latency hiding.
//   CTA = 2 warps = 2 batch columns. Lane = row pair (2l, 2l+1).
//   Warp w accumulates j in [25w, 25w+25); partials exchanged via SMEM.
//   Both warps keep h redundantly (bitwise identical: halves accumulated in
//   the same order in both warps; final add is commutative).
//   Two __syncthreads per step make single-buffered sAct/sPart race-free.
//   tanh.approx, FFMA2 matvec, shfl-bfly Jout reduce on warp0 only.

namespace {
constexpr int T_STEPS = 1024;
constexpr int B_DIM   = 4096;
constexpr int H_DIM   = 50;
constexpr int JHALF   = 25;            // j's per warp
constexpr int GRID    = B_DIM / 2;     // 2048 CTAs, 2 cols each
constexpr float DT    = 0.1f;
constexpr float OMDT  = 0.9f;
}

__device__ __forceinline__ float2 ffma2(float2 a, float2 b, float2 c) {
    unsigned long long A, B, C, D;
    __builtin_memcpy(&A, &a, 8);
    __builtin_memcpy(&B, &b, 8);
    __builtin_memcpy(&C, &c, 8);
    asm("fma.rn.f32x2 %0, %1, %2, %3;" : "=l"(D) : "l"(A), "l"(B), "l"(C));
    float2 d;
    __builtin_memcpy(&d, &D, 8);
    return d;
}

__device__ __forceinline__ float2 fadd2(float2 a, float2 b) {
    unsigned long long A, B, D;
    __builtin_memcpy(&A, &a, 8);
    __builtin_memcpy(&B, &b, 8);
    asm("add.rn.f32x2 %0, %1, %2;" : "=l"(D) : "l"(A), "l"(B));
    float2 d;
    __builtin_memcpy(&d, &D, 8);
    return d;
}

__device__ __forceinline__ float one_plus_tanh(float x) {
    float y;
    asm("tanh.approx.f32 %0, %1;" : "=f"(y) : "f"(x));
    return 1.0f + y;
}

__global__ __launch_bounds__(64, 12) void rnn_persist(
    const float* __restrict__ inpt,   // (T, B)
    const float* __restrict__ Jin,    // (H, 1)
    const float* __restrict__ Jrec,   // (H, H)
    const float* __restrict__ Jout,   // (1, H)
    const float* __restrict__ bias,   // (H, 1)
    const float* __restrict__ h0,     // (H, B)
    float* __restrict__ out)          // (T, B)
{
    __shared__ float4 sAct[H_DIM];        // sAct[j] = {a_c0, a_c0, a_c1, a_c1}
    __shared__ float4 sPart[2][32];       // per-warp matvec partials per lane

    const int tid  = threadIdx.x;
    const int lane = tid & 31;
    const int warp = tid >> 5;
    const int r    = 2 * lane;            // owned rows r, r+1
    const int j0   = warp * JHALF;        // this warp's j range
    const int gc   = blockIdx.x * 2;

    const bool v0 = (r     < H_DIM);
    const bool v1 = (r + 1 < H_DIM);

    // ---- weights for owned rows, this warp's j half, in registers ----
    float2 w[JHALF];
    #pragma unroll
    for (int j = 0; j < JHALF; j++) {
        float a = v0 ? DT * Jrec[r * H_DIM + (j0 + j)]       : 0.0f;
        float b = v1 ? DT * Jrec[(r + 1) * H_DIM + (j0 + j)] : 0.0f;
        w[j] = make_float2(a, b);
    }

    const float2 jin = make_float2(v0 ? DT * Jin[r]  : 0.0f, v1 ? DT * Jin[r + 1]  : 0.0f);
    const float2 bs  = make_float2(v0 ? DT * bias[r] : 0.0f, v1 ? DT * bias[r + 1] : 0.0f);
    const float2 jo  = make_float2(v0 ? Jout[r]      : 0.0f, v1 ? Jout[r + 1]      : 0.0f);

    // state hv[c] = (h[r][gc+c], h[r+1][gc+c]) — kept redundantly in both warps
    float2 hv[2];
    {
        float2 ra = v0 ? *reinterpret_cast<const float2*>(&h0[r * B_DIM + gc])
                       : make_float2(0.0f, 0.0f);
        float2 rb = v1 ? *reinterpret_cast<const float2*>(&h0[(r + 1) * B_DIM + gc])
                       : make_float2(0.0f, 0.0f);
        hv[0] = make_float2(ra.x, rb.x);
        hv[1] = make_float2(ra.y, rb.y);
    }

    const float* xptr = inpt + gc;
    float*       optr = out + gc;

    float2 x = *reinterpret_cast<const float2*>(xptr);   // x_0, both cols
    // which lanes of this warp write acts: split row pairs by parity between warps
    const bool my_act = (lane < JHALF) && ((lane & 1) == warp);

    for (int t = 0; t < T_STEPS; t++) {
        float2 xN = make_float2(0.0f, 0.0f);
        if (t + 1 < T_STEPS)
            xN = *reinterpret_cast<const float2*>(xptr + B_DIM);
        xptr += B_DIM;

        if (my_act) {
            float a0c0 = one_plus_tanh(hv[0].x);
            float a0c1 = one_plus_tanh(hv[1].x);
            float a1c0 = one_plus_tanh(hv[0].y);
            float a1c1 = one_plus_tanh(hv[1].y);
            sAct[r] = make_float4(a0c0, a0c0, a0c1, a0c1);
            if (v1) sAct[r + 1] = make_float4(a1c0, a1c0, a1c1, a1c1);
        }

        __syncthreads();    // bar1: acts visible CTA-wide

        float2 acc0 = make_float2(0.0f, 0.0f);
        float2 acc1 = make_float2(0.0f, 0.0f);
        #pragma unroll
        for (int j = 0; j < JHALF; j++) {
            float4 av = sAct[j0 + j];                       // broadcast LDS.128
            acc0 = ffma2(w[j], make_float2(av.x, av.y), acc0);
            acc1 = ffma2(w[j], make_float2(av.z, av.w), acc1);
        }

        sPart[warp][lane] = make_float4(acc0.x, acc0.y, acc1.x, acc1.y);

        __syncthreads();    // bar2: partials visible

        float4 ov = sPart[warp ^ 1][lane];
        float2 base0 = ffma2(jin, make_float2(x.x, x.x), bs);
        float2 base1 = ffma2(jin, make_float2(x.y, x.y), bs);
        const float2 om = make_float2(OMDT, OMDT);
        hv[0] = fadd2(fadd2(acc0, make_float2(ov.x, ov.y)), ffma2(om, hv[0], base0));
        hv[1] = fadd2(fadd2(acc1, make_float2(ov.z, ov.w)), ffma2(om, hv[1], base1));

        if (warp == 0) {
            float2 q0 = ffma2(jo, hv[0], make_float2(0.0f, 0.0f));
            float2 q1 = ffma2(jo, hv[1], make_float2(0.0f, 0.0f));
            float pc0 = q0.x + q0.y;
            float pc1 = q1.x + q1.y;
            #pragma unroll
            for (int m = 1; m < 32; m <<= 1) {
                pc0 += __shfl_xor_sync(0xFFFFFFFFu, pc0, m);
                pc1 += __shfl_xor_sync(0xFFFFFFFFu, pc1, m);
            }
            if (lane == 0)
                *reinterpret_cast<float2*>(optr) = make_float2(pc0, pc1);
        }
        optr += B_DIM;

        x = xN;
    }
}

extern "C" void kernel_launch(void* const* d_in, const int* in_sizes, int n_in,
                              void* d_out, int out_size) {
    const float* inpt = (const float*)d_in[0];
    const float* Jin  = (const float*)d_in[1];
    const float* Jrec = (const float*)d_in[2];
    const float* Jout = (const float*)d_in[3];
    const float* bias = (const float*)d_in[4];
    const float* h0   = (const float*)d_in[5];
    float* out = (float*)d_out;

    rnn_persist<<<GRID, 64>>>(inpt, Jin, Jrec, Jout, bias, h0, out);
}

// round 8
// speedup vs baseline: 1.8247x; 1.8247x over previous
#include <cuda_runtime.h>

// RNN_13855564496941: Euler RNN, T=1024, B=4096, H=50.
// R8: R5 (best: warp-autonomous, weights-in-registers, 1-warp CTAs) plus
//   scheduling fixes:
//   - output shfl-reduce for step t-1 deferred into step t's matvec window
//   - base (0.9h + dt*Jin*x + dt*bias) computed before __syncwarp
//   - rolling 1-deep prefetch of act quads in the j-loop
//   CTA = 1 warp = 2 batch columns; lane = rows (2l, 2l+1) x 2 cols.
//   dt*Jrec rows in 50 f32x2 regs/lane; acts double-buffered in SMEM as
//   duplicated (a,a) float4; one __syncwarp per step. 2048 CTAs, ~14/SM.

namespace {
constexpr int T_STEPS = 1024;
constexpr int B_DIM   = 4096;
constexpr int H_DIM   = 50;
constexpr int R_PAD   = 64;
constexpr int GRID    = B_DIM / 2;
constexpr float DT    = 0.1f;
constexpr float OMDT  = 0.9f;
}

__device__ __forceinline__ float2 ffma2(float2 a, float2 b, float2 c) {
    unsigned long long A, B, C, D;
    __builtin_memcpy(&A, &a, 8);
    __builtin_memcpy(&B, &b, 8);
    __builtin_memcpy(&C, &c, 8);
    asm("fma.rn.f32x2 %0, %1, %2, %3;" : "=l"(D) : "l"(A), "l"(B), "l"(C));
    float2 d;
    __builtin_memcpy(&d, &D, 8);
    return d;
}

__device__ __forceinline__ float one_plus_tanh(float x) {
    float y;
    asm("tanh.approx.f32 %0, %1;" : "=f"(y) : "f"(x));
    return 1.0f + y;
}

__global__ __launch_bounds__(32, 14) void rnn_persist(
    const float* __restrict__ inpt,   // (T, B)
    const float* __restrict__ Jin,    // (H, 1)
    const float* __restrict__ Jrec,   // (H, H)
    const float* __restrict__ Jout,   // (1, H)
    const float* __restrict__ bias,   // (H, 1)
    const float* __restrict__ h0,    // (H, B)
    float* __restrict__ out)          // (T, B)
{
    __shared__ float4 sAct[2][R_PAD];   // sAct[buf][row] = {a_c0,a_c0,a_c1,a_c1}

    const int lane = threadIdx.x & 31;
    const int r    = 2 * lane;
    const bool v0  = (r     < H_DIM);
    const bool v1  = (r + 1 < H_DIM);
    const int gc   = blockIdx.x * 2;

    // weights for owned rows, all j, in registers
    float2 w[H_DIM];
    #pragma unroll
    for (int j = 0; j < H_DIM; j++) {
        float a = v0 ? DT * Jrec[r * H_DIM + j]       : 0.0f;
        float b = v1 ? DT * Jrec[(r + 1) * H_DIM + j] : 0.0f;
        w[j] = make_float2(a, b);
    }

    const float2 jin = make_float2(v0 ? DT * Jin[r]  : 0.0f, v1 ? DT * Jin[r + 1]  : 0.0f);
    const float2 bs  = make_float2(v0 ? DT * bias[r] : 0.0f, v1 ? DT * bias[r + 1] : 0.0f);
    const float2 jo  = make_float2(v0 ? Jout[r]      : 0.0f, v1 ? Jout[r + 1]      : 0.0f);

    float2 hv[2];
    {
        float2 ra = v0 ? *reinterpret_cast<const float2*>(&h0[r * B_DIM + gc])
                       : make_float2(0.0f, 0.0f);
        float2 rb = v1 ? *reinterpret_cast<const float2*>(&h0[(r + 1) * B_DIM + gc])
                       : make_float2(0.0f, 0.0f);
        hv[0] = make_float2(ra.x, rb.x);
        hv[1] = make_float2(ra.y, rb.y);
    }

    const float* xptr = inpt + gc;
    float*       optr = out + gc;

    float2 x = *reinterpret_cast<const float2*>(xptr);
    float pcPrev0 = 0.0f, pcPrev1 = 0.0f;   // carried Jout partials (step t-1)
    int p = 0;

    for (int t = 0; t < T_STEPS; t++) {
        float2 xN = make_float2(0.0f, 0.0f);
        if (t + 1 < T_STEPS)
            xN = *reinterpret_cast<const float2*>(xptr + B_DIM);
        xptr += B_DIM;

        // acts for owned rows, duplicated pairs, buffer p
        {
            float a0c0 = one_plus_tanh(hv[0].x);
            float a0c1 = one_plus_tanh(hv[1].x);
            float a1c0 = one_plus_tanh(hv[0].y);
            float a1c1 = one_plus_tanh(hv[1].y);
            sAct[p][r]     = make_float4(a0c0, a0c0, a0c1, a0c1);
            sAct[p][r + 1] = make_float4(a1c0, a1c0, a1c1, a1c1);
        }

        // pre-barrier: base terms depend only on local state
        const float2 om = make_float2(OMDT, OMDT);
        float2 acc0 = ffma2(om, hv[0], ffma2(jin, make_float2(x.x, x.x), bs));
        float2 acc1 = ffma2(om, hv[1], ffma2(jin, make_float2(x.y, x.y), bs));

        __syncwarp();

        // deferred output of step t-1: shfl chain overlaps the matvec below
        if (t > 0) {
            float pc0 = pcPrev0, pc1 = pcPrev1;
            #pragma unroll
            for (int m = 1; m < 32; m <<= 1) {
                pc0 += __shfl_xor_sync(0xFFFFFFFFu, pc0, m);
                pc1 += __shfl_xor_sync(0xFFFFFFFFu, pc1, m);
            }
            if (lane == 0)
                *reinterpret_cast<float2*>(optr) = make_float2(pc0, pc1);
            optr += B_DIM;
        }

        // matvec with rolling act prefetch
        float4 av = sAct[p][0];
        #pragma unroll
        for (int j = 0; j < H_DIM; j++) {
            float4 avn = (j + 1 < H_DIM) ? sAct[p][j + 1] : av;
            acc0 = ffma2(w[j], make_float2(av.x, av.y), acc0);
            acc1 = ffma2(w[j], make_float2(av.z, av.w), acc1);
            av = avn;
        }

        hv[0] = acc0;
        hv[1] = acc1;

        // Jout partials for this step (reduced next iteration)
        float2 q0 = ffma2(jo, acc0, make_float2(0.0f, 0.0f));
        float2 q1 = ffma2(jo, acc1, make_float2(0.0f, 0.0f));
        pcPrev0 = q0.x + q0.y;
        pcPrev1 = q1.x + q1.y;

        x = xN;
        p ^= 1;
    }

    // flush final output (step T-1)
    {
        float pc0 = pcPrev0, pc1 = pcPrev1;
        #pragma unroll
        for (int m = 1; m < 32; m <<= 1) {
            pc0 += __shfl_xor_sync(0xFFFFFFFFu, pc0, m);
            pc1 += __shfl_xor_sync(0xFFFFFFFFu, pc1, m);
        }
        if (lane == 0)
            *reinterpret_cast<float2*>(optr) = make_float2(pc0, pc1);
    }
}

extern "C" void kernel_launch(void* const* d_in, const int* in_sizes, int n_in,
                              void* d_out, int out_size) {
    const float* inpt = (const float*)d_in[0];
    const float* Jin  = (const float*)d_in[1];
    const float* Jrec = (const float*)d_in[2];
    const float* Jout = (const float*)d_in[3];
    const float* bias = (const float*)d_in[4];
    const float* h0   = (const float*)d_in[5];
    float* out = (float*)d_out;

    rnn_persist<<<GRID, 32>>>(inpt, Jin, Jrec, Jout, bias, h0, out);
}

// round 9
// speedup vs baseline: 2.2162x; 1.2146x over previous
#include <cuda_runtime.h>

// RNN_13855564496941: Euler RNN, T=1024, B=4096, H=50.
// R9: attack the LDS port (L1 was 87% = binding in R8).
//   Acts stored NON-duplicated: sAct[k] = {a_{2k}c0, a_{2k}c1, a_{2k+1}c0,
//   a_{2k+1}c1} -> one LDS.128 feeds TWO j's (25 loads/step vs 50).
//   Cross-packed state: P=(h_r_c0, h_{r+1}_c1), Q=(h_r_c1, h_{r+1}_c0):
//   P's multiplicand (a_c0,a_c1) is a direct aligned subpair (0 movs);
//   Q uses the swapped pair (2 movs/j, ALU pipe has headroom).
//   Same 50 f32x2 weight regs serve both P and Q.
//   Else identical to R8: 1-warp CTAs (2 cols), tanh.approx, deferred
//   shfl-reduce output, one __syncwarp/step, 2048 CTAs ~14/SM.

namespace {
constexpr int T_STEPS = 1024;
constexpr int B_DIM   = 4096;
constexpr int H_DIM   = 50;
constexpr int KPAIR   = 25;        // 25 float4 act entries = 50 rows
constexpr int GRID    = B_DIM / 2;
constexpr float DT    = 0.1f;
constexpr float OMDT  = 0.9f;
}

__device__ __forceinline__ float2 ffma2(float2 a, float2 b, float2 c) {
    unsigned long long A, B, C, D;
    __builtin_memcpy(&A, &a, 8);
    __builtin_memcpy(&B, &b, 8);
    __builtin_memcpy(&C, &c, 8);
    asm("fma.rn.f32x2 %0, %1, %2, %3;" : "=l"(D) : "l"(A), "l"(B), "l"(C));
    float2 d;
    __builtin_memcpy(&d, &D, 8);
    return d;
}

__device__ __forceinline__ float one_plus_tanh(float x) {
    float y;
    asm("tanh.approx.f32 %0, %1;" : "=f"(y) : "f"(x));
    return 1.0f + y;
}

__global__ __launch_bounds__(32, 14) void rnn_persist(
    const float* __restrict__ inpt,   // (T, B)
    const float* __restrict__ Jin,    // (H, 1)
    const float* __restrict__ Jrec,   // (H, H)
    const float* __restrict__ Jout,   // (1, H)
    const float* __restrict__ bias,   // (H, 1)
    const float* __restrict__ h0,     // (H, B)
    float* __restrict__ out)          // (T, B)
{
    __shared__ float4 sAct[2][KPAIR + 7];  // non-duplicated acts, double-buffered

    const int lane = threadIdx.x & 31;
    const int r    = 2 * lane;
    const bool valid = (lane < KPAIR);     // lanes 0..24 own rows; 25..31 idle rows
    const int gc   = blockIdx.x * 2;

    // weights for owned rows, all j: w[j] = dt*(Jrec[r][j], Jrec[r+1][j])
    float2 w[H_DIM];
    #pragma unroll
    for (int j = 0; j < H_DIM; j++) {
        float a = valid ? DT * Jrec[r * H_DIM + j]       : 0.0f;
        float b = valid ? DT * Jrec[(r + 1) * H_DIM + j] : 0.0f;
        w[j] = make_float2(a, b);
    }

    const float2 jin = valid ? make_float2(DT * Jin[r],  DT * Jin[r + 1])  : make_float2(0.f, 0.f);
    const float2 bs  = valid ? make_float2(DT * bias[r], DT * bias[r + 1]) : make_float2(0.f, 0.f);
    const float2 jo  = valid ? make_float2(Jout[r],      Jout[r + 1])      : make_float2(0.f, 0.f);

    // cross-packed state: P = (h[r][c0], h[r+1][c1]),  Q = (h[r][c1], h[r+1][c0])
    float2 P, Q;
    {
        float2 ra = valid ? *reinterpret_cast<const float2*>(&h0[r * B_DIM + gc])
                          : make_float2(0.f, 0.f);
        float2 rb = valid ? *reinterpret_cast<const float2*>(&h0[(r + 1) * B_DIM + gc])
                          : make_float2(0.f, 0.f);
        P = make_float2(ra.x, rb.y);
        Q = make_float2(ra.y, rb.x);
    }

    const float* xptr = inpt + gc;
    float*       optr = out + gc;

    float2 x = *reinterpret_cast<const float2*>(xptr);   // (x_c0, x_c1)
    float pcPrev0 = 0.0f, pcPrev1 = 0.0f;
    int p = 0;

    for (int t = 0; t < T_STEPS; t++) {
        float2 xN = make_float2(0.0f, 0.0f);
        if (t + 1 < T_STEPS)
            xN = *reinterpret_cast<const float2*>(xptr + B_DIM);
        xptr += B_DIM;

        // acts: {a_r_c0, a_r_c1, a_{r+1}_c0, a_{r+1}_c1} = {f(P.x), f(Q.x), f(Q.y), f(P.y)}
        if (valid) {
            float a_r0  = one_plus_tanh(P.x);
            float a_r1  = one_plus_tanh(Q.x);
            float a_s0  = one_plus_tanh(Q.y);
            float a_s1  = one_plus_tanh(P.y);
            sAct[p][lane] = make_float4(a_r0, a_r1, a_s0, a_s1);
        }

        // base terms before the barrier (depend only on local state)
        const float2 om = make_float2(OMDT, OMDT);
        P = ffma2(om, P, ffma2(jin, make_float2(x.x, x.y), bs));
        Q = ffma2(om, Q, ffma2(jin, make_float2(x.y, x.x), bs));

        __syncwarp();

        // deferred output of step t-1 overlaps the matvec
        if (t > 0) {
            float pc0 = pcPrev0, pc1 = pcPrev1;
            #pragma unroll
            for (int m = 1; m < 32; m <<= 1) {
                pc0 += __shfl_xor_sync(0xFFFFFFFFu, pc0, m);
                pc1 += __shfl_xor_sync(0xFFFFFFFFu, pc1, m);
            }
            if (lane == 0)
                *reinterpret_cast<float2*>(optr) = make_float2(pc0, pc1);
            optr += B_DIM;
        }

        // matvec: one LDS.128 per TWO j's; P takes direct subpairs, Q swapped
        #pragma unroll
        for (int k = 0; k < KPAIR; k++) {
            float4 av = sAct[p][k];
            P = ffma2(w[2 * k],     make_float2(av.x, av.y), P);
            Q = ffma2(w[2 * k],     make_float2(av.y, av.x), Q);
            P = ffma2(w[2 * k + 1], make_float2(av.z, av.w), P);
            Q = ffma2(w[2 * k + 1], make_float2(av.w, av.z), Q);
        }

        // Jout partials: col0 uses (P.x, Q.y), col1 uses (Q.x, P.y)
        pcPrev0 = fmaf(jo.x, P.x, jo.y * Q.y);
        pcPrev1 = fmaf(jo.x, Q.x, jo.y * P.y);

        x = xN;
        p ^= 1;
    }

    // flush final output (step T-1)
    {
        float pc0 = pcPrev0, pc1 = pcPrev1;
        #pragma unroll
        for (int m = 1; m < 32; m <<= 1) {
            pc0 += __shfl_xor_sync(0xFFFFFFFFu, pc0, m);
            pc1 += __shfl_xor_sync(0xFFFFFFFFu, pc1, m);
        }
        if (lane == 0)
            *reinterpret_cast<float2*>(optr) = make_float2(pc0, pc1);
    }
}

extern "C" void kernel_launch(void* const* d_in, const int* in_sizes, int n_in,
                              void* d_out, int out_size) {
    const float* inpt = (const float*)d_in[0];
    const float* Jin  = (const float*)d_in[1];
    const float* Jrec = (const float*)d_in[2];
    const float* Jout = (const float*)d_in[3];
    const float* bias = (const float*)d_in[4];
    const float* h0   = (const float*)d_in[5];
    float* out = (float*)d_out;

    rnn_persist<<<GRID, 32>>>(inpt, Jin, Jrec, Jout, bias, h0, out);
}

// round 11
// speedup vs baseline: 2.3221x; 1.0478x over previous
#include <cuda_runtime.h>

// RNN_13855564496941: Euler RNN, T=1024, B=4096, H=50.
// R11 (= R10 resubmit; prior round was an infra failure, kernel never ran):
//   (1) per-step 10-shfl output butterfly replaced by batched SMEM reduce:
//       lane stores float2 Jout-partial to sOut[t&7][lane]; every 8 steps
//       lanes 0-7 sum one slot across 25 lanes (row-padded, conflict-free)
//       and do one STG.64 each. Removes a ~260-cyc MIO chain per step.
//   (2) matvec split into 4 accumulators (P/Q x even/odd k): chains 100->50
//       deep, 4-way ILP to absorb LDS latency.
//   Else R9: 1-warp CTAs (2 cols), acts non-duplicated (1 LDS.128 per 2 j),
//   cross-packed P/Q state, 50 f32x2 weight regs, tanh.approx, one
//   __syncwarp/step, 2048 CTAs (~14/SM, all resident).

namespace {
constexpr int T_STEPS = 1024;
constexpr int B_DIM   = 4096;
constexpr int H_DIM   = 50;
constexpr int KPAIR   = 25;        // float4 act entries (2 rows each)
constexpr int GRID    = B_DIM / 2;
constexpr float DT    = 0.1f;
constexpr float OMDT  = 0.9f;
}

__device__ __forceinline__ float2 ffma2(float2 a, float2 b, float2 c) {
    unsigned long long A, B, C, D;
    __builtin_memcpy(&A, &a, 8);
    __builtin_memcpy(&B, &b, 8);
    __builtin_memcpy(&C, &c, 8);
    asm("fma.rn.f32x2 %0, %1, %2, %3;" : "=l"(D) : "l"(A), "l"(B), "l"(C));
    float2 d;
    __builtin_memcpy(&d, &D, 8);
    return d;
}

__device__ __forceinline__ float2 fadd2(float2 a, float2 b) {
    unsigned long long A, B, D;
    __builtin_memcpy(&A, &a, 8);
    __builtin_memcpy(&B, &b, 8);
    asm("add.rn.f32x2 %0, %1, %2;" : "=l"(D) : "l"(A), "l"(B));
    float2 d;
    __builtin_memcpy(&d, &D, 8);
    return d;
}

__device__ __forceinline__ float one_plus_tanh(float x) {
    float y;
    asm("tanh.approx.f32 %0, %1;" : "=f"(y) : "f"(x));
    return 1.0f + y;
}

__global__ __launch_bounds__(32, 14) void rnn_persist(
    const float* __restrict__ inpt,   // (T, B)
    const float* __restrict__ Jin,    // (H, 1)
    const float* __restrict__ Jrec,   // (H, H)
    const float* __restrict__ Jout,   // (1, H)
    const float* __restrict__ bias,   // (H, 1)
    const float* __restrict__ h0,     // (H, B)
    float* __restrict__ out)          // (T, B)
{
    __shared__ float4 sAct[2][32];      // non-duplicated acts, double-buffered
    __shared__ float2 sOut[8][33];      // 8-step staging of Jout partials (padded)

    const int lane = threadIdx.x & 31;
    const int r    = 2 * lane;
    const bool valid = (lane < KPAIR);
    const int gc   = blockIdx.x * 2;

    // weights for owned rows: w[j] = dt*(Jrec[r][j], Jrec[r+1][j])
    float2 w[H_DIM];
    #pragma unroll
    for (int j = 0; j < H_DIM; j++) {
        float a = valid ? DT * Jrec[r * H_DIM + j]       : 0.0f;
        float b = valid ? DT * Jrec[(r + 1) * H_DIM + j] : 0.0f;
        w[j] = make_float2(a, b);
    }

    const float2 jin = valid ? make_float2(DT * Jin[r],  DT * Jin[r + 1])  : make_float2(0.f, 0.f);
    const float2 bs  = valid ? make_float2(DT * bias[r], DT * bias[r + 1]) : make_float2(0.f, 0.f);
    const float2 jo  = valid ? make_float2(Jout[r],      Jout[r + 1])      : make_float2(0.f, 0.f);

    // cross-packed state: P = (h[r][c0], h[r+1][c1]), Q = (h[r][c1], h[r+1][c0])
    float2 P, Q;
    {
        float2 ra = valid ? *reinterpret_cast<const float2*>(&h0[r * B_DIM + gc])
                          : make_float2(0.f, 0.f);
        float2 rb = valid ? *reinterpret_cast<const float2*>(&h0[(r + 1) * B_DIM + gc])
                          : make_float2(0.f, 0.f);
        P = make_float2(ra.x, rb.y);
        Q = make_float2(ra.y, rb.x);
    }

    const float* xptr = inpt + gc;

    float2 x = *reinterpret_cast<const float2*>(xptr);
    int p = 0;

    for (int t = 0; t < T_STEPS; t++) {
        float2 xN = make_float2(0.0f, 0.0f);
        if (t + 1 < T_STEPS)
            xN = *reinterpret_cast<const float2*>(xptr + B_DIM);
        xptr += B_DIM;

        // acts: {a_r_c0, a_r_c1, a_{r+1}_c0, a_{r+1}_c1}
        sAct[p][lane] = make_float4(one_plus_tanh(P.x), one_plus_tanh(Q.x),
                                    one_plus_tanh(Q.y), one_plus_tanh(P.y));

        // base terms (local-only) before the barrier
        const float2 om = make_float2(OMDT, OMDT);
        P = ffma2(om, P, ffma2(jin, make_float2(x.x, x.y), bs));
        Q = ffma2(om, Q, ffma2(jin, make_float2(x.y, x.x), bs));

        __syncwarp();

        // batched output flush for steps t-8..t-1; LDS/FADD chain overlaps matvec
        if ((t & 7) == 0 && t > 0 && lane < 8) {
            float2 s0 = sOut[lane][0];
            float2 s1 = sOut[lane][1];
            #pragma unroll
            for (int l = 2; l < KPAIR; l += 2) {
                s0 = fadd2(s0, sOut[lane][l]);
                if (l + 1 < KPAIR) s1 = fadd2(s1, sOut[lane][l + 1]);
            }
            float2 o = fadd2(s0, s1);
            *reinterpret_cast<float2*>(&out[(t - 8 + lane) * B_DIM + gc]) = o;
        }

        // matvec: 1 LDS.128 per 2 j; 4 accumulators (P,Q) x (even,odd k)
        float2 P1 = make_float2(0.f, 0.f), Q1 = make_float2(0.f, 0.f);
        #pragma unroll
        for (int k = 0; k < KPAIR; k += 2) {
            float4 av = sAct[p][k];
            P  = ffma2(w[2 * k],     make_float2(av.x, av.y), P);
            Q  = ffma2(w[2 * k],     make_float2(av.y, av.x), Q);
            P  = ffma2(w[2 * k + 1], make_float2(av.z, av.w), P);
            Q  = ffma2(w[2 * k + 1], make_float2(av.w, av.z), Q);
            if (k + 1 < KPAIR) {
                float4 bv = sAct[p][k + 1];
                P1 = ffma2(w[2 * k + 2], make_float2(bv.x, bv.y), P1);
                Q1 = ffma2(w[2 * k + 2], make_float2(bv.y, bv.x), Q1);
                P1 = ffma2(w[2 * k + 3], make_float2(bv.z, bv.w), P1);
                Q1 = ffma2(w[2 * k + 3], make_float2(bv.w, bv.z), Q1);
            }
        }
        P = fadd2(P, P1);
        Q = fadd2(Q, Q1);

        // Jout partial: col0 = jo.(P.x, Q.y), col1 = jo.(Q.x, P.y); stage it
        sOut[t & 7][lane] = make_float2(fmaf(jo.x, P.x, jo.y * Q.y),
                                        fmaf(jo.x, Q.x, jo.y * P.y));

        x = xN;
        p ^= 1;
    }

    // final flush (steps 1016..1023)
    __syncwarp();
    if (lane < 8) {
        float2 s0 = sOut[lane][0];
        float2 s1 = sOut[lane][1];
        #pragma unroll
        for (int l = 2; l < KPAIR; l += 2) {
            s0 = fadd2(s0, sOut[lane][l]);
            if (l + 1 < KPAIR) s1 = fadd2(s1, sOut[lane][l + 1]);
        }
        float2 o = fadd2(s0, s1);
        *reinterpret_cast<float2*>(&out[(T_STEPS - 8 + lane) * B_DIM + gc]) = o;
    }
}

extern "C" void kernel_launch(void* const* d_in, const int* in_sizes, int n_in,
                              void* d_out, int out_size) {
    const float* inpt = (const float*)d_in[0];
    const float* Jin  = (const float*)d_in[1];
    const float* Jrec = (const float*)d_in[2];
    const float* Jout = (const float*)d_in[3];
    const float* bias = (const float*)d_in[4];
    const float* h0   = (const float*)d_in[5];
    float* out = (float*)d_out;

    rnn_persist<<<GRID, 32>>>(inpt, Jin, Jrec, Jout, bias, h0, out);
}

// round 12
// speedup vs baseline: 2.6988x; 1.1622x over previous
#include <cuda_runtime.h>

// RNN_13855564496941: Euler RNN, T=1024, B=4096, H=50.
// R12: fat dual-group warps.
//   Warp = 4 batch cols as TWO independent 2-col groups (A, B) sharing ONE
//   weight-register copy (w stays 50 f32x2/lane; work per warp doubles).
//   4 independent 50-deep FFMA2 chains (PA,QA,PB,QB) -> intra-warp ILP covers
//   LDS/MUFU latency; 1024 CTAs (~1.75 warps/SMSP, regs no longer binding).
//   Jrec@1 folded into bias (acts = tanh(h), saves 4 FADD/step).
//   One LDG.128/step loads x for all 4 cols. Batched sOut flush on 16 lanes.
//   Else per R9/R11: cross-packed P/Q state, non-duplicated act quads
//   (1 LDS.128 per 2 j per group), tanh.approx, one __syncwarp/step.

namespace {
constexpr int T_STEPS = 1024;
constexpr int B_DIM   = 4096;
constexpr int H_DIM   = 50;
constexpr int KPAIR   = 25;        // float4 act entries (2 rows each)
constexpr int GRID    = B_DIM / 4; // 1024 CTAs, 4 cols each
constexpr float DT    = 0.1f;
constexpr float OMDT  = 0.9f;
}

__device__ __forceinline__ float2 ffma2(float2 a, float2 b, float2 c) {
    unsigned long long A, B, C, D;
    __builtin_memcpy(&A, &a, 8);
    __builtin_memcpy(&B, &b, 8);
    __builtin_memcpy(&C, &c, 8);
    asm("fma.rn.f32x2 %0, %1, %2, %3;" : "=l"(D) : "l"(A), "l"(B), "l"(C));
    float2 d;
    __builtin_memcpy(&d, &D, 8);
    return d;
}

__device__ __forceinline__ float2 fadd2(float2 a, float2 b) {
    unsigned long long A, B, D;
    __builtin_memcpy(&A, &a, 8);
    __builtin_memcpy(&B, &b, 8);
    asm("add.rn.f32x2 %0, %1, %2;" : "=l"(D) : "l"(A), "l"(B));
    float2 d;
    __builtin_memcpy(&d, &D, 8);
    return d;
}

__device__ __forceinline__ float tanh_fast(float x) {
    float y;
    asm("tanh.approx.f32 %0, %1;" : "=f"(y) : "f"(x));
    return y;
}

__global__ __launch_bounds__(32, 7) void rnn_persist(
    const float* __restrict__ inpt,   // (T, B)
    const float* __restrict__ Jin,    // (H, 1)
    const float* __restrict__ Jrec,   // (H, H)
    const float* __restrict__ Jout,   // (1, H)
    const float* __restrict__ bias,   // (H, 1)
    const float* __restrict__ h0,     // (H, B)
    float* __restrict__ out)          // (T, B)
{
    __shared__ float4 sAct[2][2][32];    // [buf][group][lane], non-duplicated
    __shared__ float2 sOut[8][2][33];    // [slot][group][lane], padded rows

    const int lane = threadIdx.x & 31;
    const int r    = 2 * lane;
    const bool valid = (lane < KPAIR);
    const int gc   = blockIdx.x * 4;     // group A: gc,gc+1; group B: gc+2,gc+3

    // weights + folded bias: bs = dt*bias + dt*Jrec@1 (row sums of w)
    float2 w[H_DIM];
    float2 bs = valid ? make_float2(DT * bias[r], DT * bias[r + 1]) : make_float2(0.f, 0.f);
    #pragma unroll
    for (int j = 0; j < H_DIM; j++) {
        float a = valid ? DT * Jrec[r * H_DIM + j]       : 0.0f;
        float b = valid ? DT * Jrec[(r + 1) * H_DIM + j] : 0.0f;
        w[j] = make_float2(a, b);
        bs = fadd2(bs, w[j]);
    }

    const float2 jin = valid ? make_float2(DT * Jin[r], DT * Jin[r + 1]) : make_float2(0.f, 0.f);
    const float2 jo  = valid ? make_float2(Jout[r],     Jout[r + 1])     : make_float2(0.f, 0.f);

    // cross-packed state per group: P=(h[r][c0], h[r+1][c1]), Q=(h[r][c1], h[r+1][c0])
    float2 PA, QA, PB, QB;
    {
        float4 ra = valid ? *reinterpret_cast<const float4*>(&h0[r * B_DIM + gc])
                          : make_float4(0.f, 0.f, 0.f, 0.f);
        float4 rb = valid ? *reinterpret_cast<const float4*>(&h0[(r + 1) * B_DIM + gc])
                          : make_float4(0.f, 0.f, 0.f, 0.f);
        PA = make_float2(ra.x, rb.y);  QA = make_float2(ra.y, rb.x);
        PB = make_float2(ra.z, rb.w);  QB = make_float2(ra.w, rb.z);
    }

    const float* xptr = inpt + gc;
    float4 x4 = *reinterpret_cast<const float4*>(xptr);   // x_0 for all 4 cols
    int p = 0;

    for (int t = 0; t < T_STEPS; t++) {
        float4 x4n = make_float4(0.f, 0.f, 0.f, 0.f);
        if (t + 1 < T_STEPS)
            x4n = *reinterpret_cast<const float4*>(xptr + B_DIM);
        xptr += B_DIM;

        // acts = tanh(h) (1+ folded into bias): {a_r_c0, a_r_c1, a_{r+1}_c0, a_{r+1}_c1}
        sAct[p][0][lane] = make_float4(tanh_fast(PA.x), tanh_fast(QA.x),
                                       tanh_fast(QA.y), tanh_fast(PA.y));
        sAct[p][1][lane] = make_float4(tanh_fast(PB.x), tanh_fast(QB.x),
                                       tanh_fast(QB.y), tanh_fast(PB.y));

        // base terms (local-only) before the barrier
        const float2 om = make_float2(OMDT, OMDT);
        PA = ffma2(om, PA, ffma2(jin, make_float2(x4.x, x4.y), bs));
        QA = ffma2(om, QA, ffma2(jin, make_float2(x4.y, x4.x), bs));
        PB = ffma2(om, PB, ffma2(jin, make_float2(x4.z, x4.w), bs));
        QB = ffma2(om, QB, ffma2(jin, make_float2(x4.w, x4.z), bs));

        __syncwarp();

        // batched output flush (steps t-8..t-1), 16 lanes: 8 rows x 2 groups
        if ((t & 7) == 0 && t > 0 && lane < 16) {
            int g = lane >> 3, L = lane & 7;
            float2 s0 = sOut[L][g][0];
            float2 s1 = sOut[L][g][1];
            #pragma unroll
            for (int l = 2; l < KPAIR; l += 2) {
                s0 = fadd2(s0, sOut[L][g][l]);
                if (l + 1 < KPAIR) s1 = fadd2(s1, sOut[L][g][l + 1]);
            }
            *reinterpret_cast<float2*>(&out[(t - 8 + L) * B_DIM + gc + 2 * g]) = fadd2(s0, s1);
        }

        // matvec: per k, 2 LDS.128 feed 8 FFMA2 across 4 independent chains
        #pragma unroll
        for (int k = 0; k < KPAIR; k++) {
            float4 avA = sAct[p][0][k];
            float4 avB = sAct[p][1][k];
            PA = ffma2(w[2 * k],     make_float2(avA.x, avA.y), PA);
            QA = ffma2(w[2 * k],     make_float2(avA.y, avA.x), QA);
            PB = ffma2(w[2 * k],     make_float2(avB.x, avB.y), PB);
            QB = ffma2(w[2 * k],     make_float2(avB.y, avB.x), QB);
            PA = ffma2(w[2 * k + 1], make_float2(avA.z, avA.w), PA);
            QA = ffma2(w[2 * k + 1], make_float2(avA.w, avA.z), QA);
            PB = ffma2(w[2 * k + 1], make_float2(avB.z, avB.w), PB);
            QB = ffma2(w[2 * k + 1], make_float2(avB.w, avB.z), QB);
        }

        // stage Jout partials: colpair (c0,c1) = (jo.(P.x,Q.y), jo.(Q.x,P.y))
        sOut[t & 7][0][lane] = make_float2(fmaf(jo.x, PA.x, jo.y * QA.y),
                                           fmaf(jo.x, QA.x, jo.y * PA.y));
        sOut[t & 7][1][lane] = make_float2(fmaf(jo.x, PB.x, jo.y * QB.y),
                                           fmaf(jo.x, QB.x, jo.y * PB.y));

        x4 = x4n;
        p ^= 1;
    }

    // final flush (steps 1016..1023)
    __syncwarp();
    if (lane < 16) {
        int g = lane >> 3, L = lane & 7;
        float2 s0 = sOut[L][g][0];
        float2 s1 = sOut[L][g][1];
        #pragma unroll
        for (int l = 2; l < KPAIR; l += 2) {
            s0 = fadd2(s0, sOut[L][g][l]);
            if (l + 1 < KPAIR) s1 = fadd2(s1, sOut[L][g][l + 1]);
        }
        *reinterpret_cast<float2*>(&out[(T_STEPS - 8 + L) * B_DIM + gc + 2 * g]) = fadd2(s0, s1);
    }
}

extern "C" void kernel_launch(void* const* d_in, const int* in_sizes, int n_in,
                              void* d_out, int out_size) {
    const float* inpt = (const float*)d_in[0];
    const float* Jin  = (const float*)d_in[1];
    const float* Jrec = (const float*)d_in[2];
    const float* Jout = (const float*)d_in[3];
    const float* bias = (const float*)d_in[4];
    const float* h0   = (const float*)d_in[5];
    float* out = (float*)d_out;

    rnn_persist<<<GRID, 32>>>(inpt, Jin, Jrec, Jout, bias, h0, out);
}